// round 1
// baseline (speedup 1.0000x reference)
#include <cuda_runtime.h>

#define NB 1024   // batch rows
#define NL 512    // labels per row
#define NT 256    // threads per block
#define NW 8      // warps per block
#define NC (NL/NT)  // column chunks per thread = 2

__device__ float g_row[NB];

__inline__ __device__ float warpSum(float v) {
#pragma unroll
    for (int o = 16; o; o >>= 1) v += __shfl_xor_sync(0xffffffffu, v, o);
    return v;
}

__global__ __launch_bounds__(NT) void row_kernel(const float* __restrict__ outp,
                                                 const int* __restrict__ tgt) {
    __shared__ __align__(16) float spos[NL];
    __shared__ float sneg[NL];
    __shared__ int wP[NC * NW];   // per (chunk, warp) positive counts
    __shared__ int wN[NC * NW];   // per (chunk, warp) negative counts
    __shared__ float s0[NW], s1[NW], s2[NW];

    const int row  = blockIdx.x;
    const int tid  = threadIdx.x;
    const int lane = tid & 31;
    const int wid  = tid >> 5;
    const unsigned lmask = (1u << lane) - 1u;

    const float* orow = outp + row * NL;
    const int*   trow = tgt  + row * NL;

    // ---- pass 1: load, ballot, per-(chunk,warp) counts; calib partial sums ----
    float vv[NC];
    bool  isp[NC];
    unsigned bm[NC];
    float pos_sum = 0.f, neg_sum = 0.f;
#pragma unroll
    for (int c = 0; c < NC; c++) {
        int col = tid + c * NT;
        float v = orow[col];
        bool p  = (trow[col] != 0);
        vv[c] = v; isp[c] = p;
        bm[c] = __ballot_sync(0xffffffffu, p);
        if (lane == 0) {
            wP[c * NW + wid] = __popc(bm[c]);
            wN[c * NW + wid] = 32 - __popc(bm[c]);
        }
        if (p) pos_sum += fmaxf(1.f - v, 0.f);
        else   neg_sum += fmaxf(1.f + v, 0.f);
    }
    __syncthreads();

    // ---- pass 2: deterministic exclusive scan over (chunk, warp) lexicographic order ----
    int n_p = 0, n_n = 0;
#pragma unroll
    for (int i = 0; i < NC * NW; i++) { n_p += wP[i]; n_n += wN[i]; }

#pragma unroll
    for (int c = 0; c < NC; c++) {
        int idx = c * NW + wid;
        int baseP = 0, baseN = 0;
        for (int i = 0; i < idx; i++) { baseP += wP[i]; baseN += wN[i]; }
        if (isp[c]) spos[baseP + __popc(bm[c] & lmask)] = vv[c];
        else        sneg[baseN + __popc(~bm[c] & lmask)] = vv[c];
    }
    __syncthreads();

    // ---- pad positives to multiple of 4 with +huge sentinel (contributes 0) ----
    for (int k = n_p + tid; k < NL; k += NT) spos[k] = 3.0e30f;
    __syncthreads();

    // ---- pairwise hinge: each thread owns negatives j = tid, tid+NT, ... ----
    const int np4 = (n_p + 3) & ~3;
    float acc = 0.f;
    for (int j = tid; j < n_n; j += NT) {
        const float cc = 1.f + sneg[j];
        float a0 = 0.f, a1 = 0.f, a2 = 0.f, a3 = 0.f;
        for (int k = 0; k < np4; k += 4) {
            float4 p = *reinterpret_cast<const float4*>(&spos[k]);
            a0 += fmaxf(cc - p.x, 0.f);
            a1 += fmaxf(cc - p.y, 0.f);
            a2 += fmaxf(cc - p.z, 0.f);
            a3 += fmaxf(cc - p.w, 0.f);
        }
        acc += (a0 + a1) + (a2 + a3);
    }

    // ---- block reduce (acc, pos_sum, neg_sum) ----
    float r0 = warpSum(acc);
    float r1 = warpSum(pos_sum);
    float r2 = warpSum(neg_sum);
    if (lane == 0) { s0[wid] = r0; s1[wid] = r1; s2[wid] = r2; }
    __syncthreads();

    if (tid == 0) {
        float ps = 0.f, qs = 0.f, ns = 0.f;
#pragma unroll
        for (int w = 0; w < NW; w++) { ps += s0[w]; qs += s1[w]; ns += s2[w]; }
        float pos_calib = (n_p > 0) ? qs / (float)n_p : 0.f;
        float neg_calib = (n_n > 0) ? ns / (float)n_n : 0.f;
        long long denom = (long long)n_p * (long long)n_n;
        float hinge;
        if (denom > 0)      hinge = ps / (float)denom;
        else if (n_p > 0)   hinge = pos_calib;
        else if (n_n > 0)   hinge = neg_calib;
        else                hinge = 1.f;
        g_row[row] = hinge + neg_calib + pos_calib;
    }
}

__global__ __launch_bounds__(NT) void reduce_kernel(float* __restrict__ out) {
    const int tid = threadIdx.x;
    float v = 0.f;
#pragma unroll
    for (int i = tid; i < NB; i += NT) v += g_row[i];
    v = warpSum(v);
    __shared__ float s[NW];
    if ((tid & 31) == 0) s[tid >> 5] = v;
    __syncthreads();
    if (tid == 0) {
        float t = 0.f;
#pragma unroll
        for (int w = 0; w < NW; w++) t += s[w];
        out[0] = t / (float)NB;
    }
}

extern "C" void kernel_launch(void* const* d_in, const int* in_sizes, int n_in,
                              void* d_out, int out_size) {
    const float* outputs = (const float*)d_in[0];
    const int*   targets = (const int*)d_in[1];
    row_kernel<<<NB, NT>>>(outputs, targets);
    reduce_kernel<<<1, NT>>>((float*)d_out);
}

// round 2
// speedup vs baseline: 1.0923x; 1.0923x over previous
#include <cuda_runtime.h>

#define NB 1024   // batch rows
#define NL 512    // labels per row
#define NT 256    // threads per block
#define NW 8      // warps per block
#define NC (NL/NT)  // column chunks per thread = 2

__device__ float g_row[NB];
__device__ int   g_cnt = 0;   // self-resetting across graph replays

__inline__ __device__ float warpSum(float v) {
#pragma unroll
    for (int o = 16; o; o >>= 1) v += __shfl_xor_sync(0xffffffffu, v, o);
    return v;
}

__global__ __launch_bounds__(NT) void row_kernel(const float* __restrict__ outp,
                                                 const int* __restrict__ tgt,
                                                 float* __restrict__ out) {
    __shared__ __align__(16) float spos[NL];
    __shared__ float sneg[NL];
    __shared__ int wP[NC * NW];   // per (chunk, warp) positive counts
    __shared__ int wN[NC * NW];   // per (chunk, warp) negative counts
    __shared__ float s0[NW], s1[NW], s2[NW];
    __shared__ int amLast;

    const int row  = blockIdx.x;
    const int tid  = threadIdx.x;
    const int lane = tid & 31;
    const int wid  = tid >> 5;
    const unsigned lmask = (1u << lane) - 1u;

    const float* orow = outp + row * NL;
    const int*   trow = tgt  + row * NL;

    // ---- pass 1: load, ballot, per-(chunk,warp) counts; calib partial sums ----
    float vv[NC];
    bool  isp[NC];
    unsigned bm[NC];
    float pos_sum = 0.f, neg_sum = 0.f;
#pragma unroll
    for (int c = 0; c < NC; c++) {
        int col = tid + c * NT;
        float v = orow[col];
        bool p  = (trow[col] != 0);
        vv[c] = v; isp[c] = p;
        bm[c] = __ballot_sync(0xffffffffu, p);
        if (lane == 0) {
            wP[c * NW + wid] = __popc(bm[c]);
            wN[c * NW + wid] = 32 - __popc(bm[c]);
        }
        if (p) pos_sum += fmaxf(1.f - v, 0.f);
        else   neg_sum += fmaxf(1.f + v, 0.f);
    }
    __syncthreads();

    // ---- pass 2: deterministic exclusive scan over (chunk, warp) lexicographic order ----
    int n_p = 0, n_n = 0;
#pragma unroll
    for (int i = 0; i < NC * NW; i++) { n_p += wP[i]; n_n += wN[i]; }

#pragma unroll
    for (int c = 0; c < NC; c++) {
        int idx = c * NW + wid;
        int baseP = 0, baseN = 0;
        for (int i = 0; i < idx; i++) { baseP += wP[i]; baseN += wN[i]; }
        if (isp[c]) spos[baseP + __popc(bm[c] & lmask)] = vv[c];
        else        sneg[baseN + __popc(~bm[c] & lmask)] = vv[c];
    }
    __syncthreads();

    // ---- pad positives to multiple of 4 with +huge sentinel (contributes 0) ----
    for (int k = n_p + tid; k < NL; k += NT) spos[k] = 3.0e30f;
    __syncthreads();

    const int np4 = (n_p + 3) & ~3;
    const int cpn = np4 >> 2;          // float4 chunks per negative
    float acc = 0.f;

    // ---- phase 1: negatives 0..min(n_n,NT)-1, one per thread, single sweep ----
    // Positives broadcast via LDS.128 (all lanes same address -> conflict-free).
    if (tid < n_n) {
        const float cc = 1.f + sneg[tid];
        float a0 = 0.f, a1 = 0.f, a2 = 0.f, a3 = 0.f;
        for (int k = 0; k < np4; k += 4) {
            float4 p = *reinterpret_cast<const float4*>(&spos[k]);
            a0 += fmaxf(cc - p.x, 0.f);
            a1 += fmaxf(cc - p.y, 0.f);
            a2 += fmaxf(cc - p.z, 0.f);
            a3 += fmaxf(cc - p.w, 0.f);
        }
        acc = (a0 + a1) + (a2 + a3);
    }

    // ---- phase 2: excess negatives (n_n > NT), flattened pair-chunk work units ----
    // At most ~50 negatives x ~64 chunks spread over 256 threads: balanced, tiny.
    if (n_n > NT) {
        const int total = (n_n - NT) * cpn;
        for (int t = tid; t < total; t += NT) {
            const int j = NT + t / cpn;
            const int k = (t - (j - NT) * cpn) << 2;
            const float cc = 1.f + sneg[j];
            float4 p = *reinterpret_cast<const float4*>(&spos[k]);
            float b0 = fmaxf(cc - p.x, 0.f) + fmaxf(cc - p.y, 0.f);
            float b1 = fmaxf(cc - p.z, 0.f) + fmaxf(cc - p.w, 0.f);
            acc += b0 + b1;
        }
    }

    // ---- block reduce (acc, pos_sum, neg_sum) ----
    float r0 = warpSum(acc);
    float r1 = warpSum(pos_sum);
    float r2 = warpSum(neg_sum);
    if (lane == 0) { s0[wid] = r0; s1[wid] = r1; s2[wid] = r2; }
    __syncthreads();

    if (tid == 0) {
        float ps = 0.f, qs = 0.f, ns = 0.f;
#pragma unroll
        for (int w = 0; w < NW; w++) { ps += s0[w]; qs += s1[w]; ns += s2[w]; }
        float pos_calib = (n_p > 0) ? qs / (float)n_p : 0.f;
        float neg_calib = (n_n > 0) ? ns / (float)n_n : 0.f;
        long long denom = (long long)n_p * (long long)n_n;
        float hinge;
        if (denom > 0)      hinge = ps / (float)denom;
        else if (n_p > 0)   hinge = pos_calib;
        else if (n_n > 0)   hinge = neg_calib;
        else                hinge = 1.f;
        g_row[row] = hinge + neg_calib + pos_calib;
        __threadfence();
        int old = atomicAdd(&g_cnt, 1);
        amLast = (old == NB - 1);
    }
    __syncthreads();

    // ---- last block: deterministic final mean over g_row ----
    if (amLast) {
        __threadfence();  // acquire all g_row writes
        float v = 0.f;
#pragma unroll
        for (int i = tid; i < NB; i += NT) v += g_row[i];
        v = warpSum(v);
        if (lane == 0) s0[wid] = v;
        __syncthreads();
        if (tid == 0) {
            float t = 0.f;
#pragma unroll
            for (int w = 0; w < NW; w++) t += s0[w];
            out[0] = t / (float)NB;
            g_cnt = 0;   // reset for next graph replay
        }
    }
}

extern "C" void kernel_launch(void* const* d_in, const int* in_sizes, int n_in,
                              void* d_out, int out_size) {
    const float* outputs = (const float*)d_in[0];
    const int*   targets = (const int*)d_in[1];
    row_kernel<<<NB, NT>>>(outputs, targets, (float*)d_out);
}

// round 3
// speedup vs baseline: 1.2480x; 1.1426x over previous
#include <cuda_runtime.h>
#include <cuda_fp16.h>

#define NB 1024   // batch rows
#define NL 512    // labels per row
#define NT 256    // threads per block
#define NW 8      // warps per block
#define NC (NL/NT)  // column chunks per thread = 2

__device__ float g_row[NB];
__device__ int   g_cnt = 0;   // self-resetting across graph replays

__inline__ __device__ float warpSum(float v) {
#pragma unroll
    for (int o = 16; o; o >>= 1) v += __shfl_xor_sync(0xffffffffu, v, o);
    return v;
}

__device__ __forceinline__ __half2 h2_from_u32(unsigned u) {
    __half2 h;
    *reinterpret_cast<unsigned*>(&h) = u;
    return h;
}

__global__ __launch_bounds__(NT) void row_kernel(const float* __restrict__ outp,
                                                 const int* __restrict__ tgt,
                                                 float* __restrict__ out) {
    __shared__ __align__(16) __half2 sposh[NL];  // negated, lane-duplicated positives
    __shared__ float sneg[NL];
    __shared__ int wP[NC * NW];   // per (chunk, warp) positive counts
    __shared__ int wN[NC * NW];   // per (chunk, warp) negative counts
    __shared__ float s0[NW], s1[NW], s2[NW];
    __shared__ int amLast;

    const int row  = blockIdx.x;
    const int tid  = threadIdx.x;
    const int lane = tid & 31;
    const int wid  = tid >> 5;
    const unsigned lmask = (1u << lane) - 1u;

    const float* orow = outp + row * NL;
    const int*   trow = tgt  + row * NL;

    // ---- pass 1: load, ballot, per-(chunk,warp) counts; calib partial sums (fp32) ----
    float vv[NC];
    bool  isp[NC];
    unsigned bm[NC];
    float pos_sum = 0.f, neg_sum = 0.f;
#pragma unroll
    for (int c = 0; c < NC; c++) {
        int col = tid + c * NT;
        float v = orow[col];
        bool p  = (trow[col] != 0);
        vv[c] = v; isp[c] = p;
        bm[c] = __ballot_sync(0xffffffffu, p);
        if (lane == 0) {
            wP[c * NW + wid] = __popc(bm[c]);
            wN[c * NW + wid] = 32 - __popc(bm[c]);
        }
        if (p) pos_sum += fmaxf(1.f - v, 0.f);
        else   neg_sum += fmaxf(1.f + v, 0.f);
    }
    __syncthreads();

    // ---- pass 2: deterministic exclusive scan, scatter compacted values ----
    int n_p = 0, n_n = 0;
#pragma unroll
    for (int i = 0; i < NC * NW; i++) { n_p += wP[i]; n_n += wN[i]; }

#pragma unroll
    for (int c = 0; c < NC; c++) {
        int idx = c * NW + wid;
        int baseP = 0, baseN = 0;
        for (int i = 0; i < idx; i++) { baseP += wP[i]; baseN += wN[i]; }
        if (isp[c]) sposh[baseP + __popc(bm[c] & lmask)] =
                        __half2half2(__float2half_rn(-vv[c]));   // negated, duplicated
        else        sneg[baseN + __popc(~bm[c] & lmask)] = vv[c];
    }
    __syncthreads();

    // ---- pad positives to multiple of 16 with -inf (contributes exactly 0) ----
    const int np16 = (n_p + 15) & ~15;
    for (int k = n_p + tid; k < np16; k += NT)
        sposh[k] = __half2half2(__float2half_rn(-3.0e30f));  // -> half -inf
    __syncthreads();

    // ---- pairwise hinge: thread t owns negatives (2t, 2t+1) packed in half2 lanes ----
    float facc = 0.f;
    const int t2 = tid << 1;
    if (t2 < n_n) {
        const float ca = 1.f + sneg[t2];
        const float cb = (t2 + 1 < n_n) ? 1.f + sneg[t2 + 1] : -3.0e30f;  // -> -inf lane
        const __half2 cc2 = __floats2half2_rn(ca, cb);
        const __half2 z   = __float2half2_rn(0.f);
        const uint4* base = reinterpret_cast<const uint4*>(sposh);
        const int nChunks = np16 >> 4;   // 16 positives (4 x LDS.128) per chunk
        for (int ch = 0; ch < nChunks; ch++) {
            __half2 a0 = z, a1 = z, a2 = z, a3 = z;
#pragma unroll
            for (int u = 0; u < 4; u++) {
                uint4 w = base[(ch << 2) + u];
                a0 = __hadd2(a0, __hmax2(__hadd2(cc2, h2_from_u32(w.x)), z));
                a1 = __hadd2(a1, __hmax2(__hadd2(cc2, h2_from_u32(w.y)), z));
                a2 = __hadd2(a2, __hmax2(__hadd2(cc2, h2_from_u32(w.z)), z));
                a3 = __hadd2(a3, __hmax2(__hadd2(cc2, h2_from_u32(w.w)), z));
            }
            __half2 s = __hadd2(__hadd2(a0, a1), __hadd2(a2, a3));
            facc += __low2float(s) + __high2float(s);   // fp32 flush every 16 positives
        }
    }

    // ---- block reduce (pair acc, pos_sum, neg_sum) ----
    float r0 = warpSum(facc);
    float r1 = warpSum(pos_sum);
    float r2 = warpSum(neg_sum);
    if (lane == 0) { s0[wid] = r0; s1[wid] = r1; s2[wid] = r2; }
    __syncthreads();

    if (tid == 0) {
        float ps = 0.f, qs = 0.f, ns = 0.f;
#pragma unroll
        for (int w = 0; w < NW; w++) { ps += s0[w]; qs += s1[w]; ns += s2[w]; }
        float pos_calib = (n_p > 0) ? qs / (float)n_p : 0.f;
        float neg_calib = (n_n > 0) ? ns / (float)n_n : 0.f;
        long long denom = (long long)n_p * (long long)n_n;
        float hinge;
        if (denom > 0)      hinge = ps / (float)denom;
        else if (n_p > 0)   hinge = pos_calib;
        else if (n_n > 0)   hinge = neg_calib;
        else                hinge = 1.f;
        g_row[row] = hinge + neg_calib + pos_calib;
        __threadfence();
        int old = atomicAdd(&g_cnt, 1);
        amLast = (old == NB - 1);
    }
    __syncthreads();

    // ---- last block: deterministic final mean over g_row ----
    if (amLast) {
        __threadfence();  // acquire all g_row writes
        float v = 0.f;
#pragma unroll
        for (int i = tid; i < NB; i += NT) v += g_row[i];
        v = warpSum(v);
        if (lane == 0) s0[wid] = v;
        __syncthreads();
        if (tid == 0) {
            float t = 0.f;
#pragma unroll
            for (int w = 0; w < NW; w++) t += s0[w];
            out[0] = t / (float)NB;
            g_cnt = 0;   // reset for next graph replay
        }
    }
}

extern "C" void kernel_launch(void* const* d_in, const int* in_sizes, int n_in,
                              void* d_out, int out_size) {
    const float* outputs = (const float*)d_in[0];
    const int*   targets = (const int*)d_in[1];
    row_kernel<<<NB, NT>>>(outputs, targets, (float*)d_out);
}

// round 4
// speedup vs baseline: 1.4137x; 1.1327x over previous
#include <cuda_runtime.h>
#include <cuda_fp16.h>

#define NB 1024   // batch rows
#define NL 512    // labels per row
#define NT 256    // threads per block
#define NW 8      // warps per block
#define NC (NL/NT)  // column chunks per thread = 2

__device__ float g_row[NB];
__device__ int   g_cnt = 0;   // self-resetting across graph replays

__inline__ __device__ float warpSum(float v) {
#pragma unroll
    for (int o = 16; o; o >>= 1) v += __shfl_xor_sync(0xffffffffu, v, o);
    return v;
}

__device__ __forceinline__ __half2 h2_from_u32(unsigned u) {
    __half2 h;
    *reinterpret_cast<unsigned*>(&h) = u;
    return h;
}

__global__ __launch_bounds__(NT) void row_kernel(const float* __restrict__ outp,
                                                 const int* __restrict__ tgt,
                                                 float* __restrict__ out) {
    __shared__ __align__(16) __half sposh[NL];   // negated positives, compacted
    __shared__ float sneg[NL];
    __shared__ int wP[NC * NW];   // per (chunk, warp) positive counts
    __shared__ int wN[NC * NW];   // per (chunk, warp) negative counts
    __shared__ float s0[NW], s1[NW], s2[NW];
    __shared__ int amLast;

    const int row  = blockIdx.x;
    const int tid  = threadIdx.x;
    const int lane = tid & 31;
    const int wid  = tid >> 5;
    const unsigned lmask = (1u << lane) - 1u;

    const float* orow = outp + row * NL;
    const int*   trow = tgt  + row * NL;

    // ---- pass 1: load, ballot, per-(chunk,warp) counts; calib partial sums (fp32) ----
    float vv[NC];
    bool  isp[NC];
    unsigned bm[NC];
    float pos_sum = 0.f, neg_sum = 0.f;
#pragma unroll
    for (int c = 0; c < NC; c++) {
        int col = tid + c * NT;
        float v = orow[col];
        bool p  = (trow[col] != 0);
        vv[c] = v; isp[c] = p;
        bm[c] = __ballot_sync(0xffffffffu, p);
        if (lane == 0) {
            wP[c * NW + wid] = __popc(bm[c]);
            wN[c * NW + wid] = 32 - __popc(bm[c]);
        }
        if (p) pos_sum += fmaxf(1.f - v, 0.f);
        else   neg_sum += fmaxf(1.f + v, 0.f);
    }
    __syncthreads();

    // ---- pass 2: deterministic scan + scatter; fold in sentinel padding ----
    int n_p = 0, n_n = 0;
#pragma unroll
    for (int i = 0; i < NC * NW; i++) { n_p += wP[i]; n_n += wN[i]; }
    const int np32 = (n_p + 31) & ~31;   // pad positives to multiple of 32

#pragma unroll
    for (int c = 0; c < NC; c++) {
        int idx = c * NW + wid;
        int baseP = 0, baseN = 0;
        for (int i = 0; i < idx; i++) { baseP += wP[i]; baseN += wN[i]; }
        if (isp[c]) sposh[baseP + __popc(bm[c] & lmask)] = __float2half_rn(-vv[c]);
        else        sneg[baseN + __popc(~bm[c] & lmask)] = vv[c];
    }
    // sentinel pad (indices >= n_p, disjoint from scatter writes above)
    for (int k = n_p + tid; k < np32; k += NT)
        sposh[k] = __float2half_rn(-3.0e30f);   // -> half -inf, contributes exactly 0
    __syncthreads();

    const uint4* base = reinterpret_cast<const uint4*>(sposh);  // 8 positives / word
    const int nW4 = np32 >> 3;
    const __half2 z = __float2half2_rn(0.f);
    float facc = 0.f;

    // ---- phase 1: thread t owns negative t (all min(n_n,256) threads active) ----
    if (tid < n_n) {
        const __half2 cc2 = __float2half2_rn(1.f + sneg[tid]);  // duplicated negative
        for (int w = 0; w < nW4; w += 4) {        // 32 positives per superchunk
            __half2 a0 = z, a1 = z, a2 = z, a3 = z;
#pragma unroll
            for (int u = 0; u < 4; u++) {
                uint4 q = base[w + u];
                a0 = __hadd2(a0, __hmax2(__hadd2(cc2, h2_from_u32(q.x)), z));
                a1 = __hadd2(a1, __hmax2(__hadd2(cc2, h2_from_u32(q.y)), z));
                a2 = __hadd2(a2, __hmax2(__hadd2(cc2, h2_from_u32(q.z)), z));
                a3 = __hadd2(a3, __hmax2(__hadd2(cc2, h2_from_u32(q.w)), z));
            }
            __half2 s = __hadd2(__hadd2(a0, a1), __hadd2(a2, a3));
            facc += __low2float(s) + __high2float(s);   // fp32 flush / 32 positives
        }
    }

    // ---- phase 2: excess negatives (n_n > 256): one warp per extra negative ----
    // Lanes stride the positive words; partials go straight into facc (warp-summed below).
    for (int j = NT + wid; j < n_n; j += NW) {
        const __half2 cc2 = __float2half2_rn(1.f + sneg[j]);  // broadcast, conflict-free
        for (int w = lane; w < nW4; w += 32) {
            uint4 q = base[w];
            __half2 b0 = __hadd2(__hmax2(__hadd2(cc2, h2_from_u32(q.x)), z),
                                 __hmax2(__hadd2(cc2, h2_from_u32(q.y)), z));
            __half2 b1 = __hadd2(__hmax2(__hadd2(cc2, h2_from_u32(q.z)), z),
                                 __hmax2(__hadd2(cc2, h2_from_u32(q.w)), z));
            __half2 s = __hadd2(b0, b1);
            facc += __low2float(s) + __high2float(s);
        }
    }

    // ---- block reduce (pair acc, pos_sum, neg_sum) ----
    float r0 = warpSum(facc);
    float r1 = warpSum(pos_sum);
    float r2 = warpSum(neg_sum);
    if (lane == 0) { s0[wid] = r0; s1[wid] = r1; s2[wid] = r2; }
    __syncthreads();

    if (tid == 0) {
        float ps = 0.f, qs = 0.f, ns = 0.f;
#pragma unroll
        for (int w = 0; w < NW; w++) { ps += s0[w]; qs += s1[w]; ns += s2[w]; }
        float pos_calib = (n_p > 0) ? qs / (float)n_p : 0.f;
        float neg_calib = (n_n > 0) ? ns / (float)n_n : 0.f;
        long long denom = (long long)n_p * (long long)n_n;
        float hinge;
        if (denom > 0)      hinge = ps / (float)denom;
        else if (n_p > 0)   hinge = pos_calib;
        else if (n_n > 0)   hinge = neg_calib;
        else                hinge = 1.f;
        g_row[row] = hinge + neg_calib + pos_calib;
        __threadfence();
        int old = atomicAdd(&g_cnt, 1);
        amLast = (old == NB - 1);
    }
    __syncthreads();

    // ---- last block: deterministic final mean over g_row ----
    if (amLast) {
        __threadfence();  // acquire all g_row writes
        float v = 0.f;
#pragma unroll
        for (int i = tid; i < NB; i += NT) v += g_row[i];
        v = warpSum(v);
        if (lane == 0) s0[wid] = v;
        __syncthreads();
        if (tid == 0) {
            float t = 0.f;
#pragma unroll
            for (int w = 0; w < NW; w++) t += s0[w];
            out[0] = t / (float)NB;
            g_cnt = 0;   // reset for next graph replay
        }
    }
}

extern "C" void kernel_launch(void* const* d_in, const int* in_sizes, int n_in,
                              void* d_out, int out_size) {
    const float* outputs = (const float*)d_in[0];
    const int*   targets = (const int*)d_in[1];
    row_kernel<<<NB, NT>>>(outputs, targets, (float*)d_out);
}

// round 5
// speedup vs baseline: 1.9305x; 1.3656x over previous
#include <cuda_runtime.h>

#define NB 1024   // batch rows
#define NL 512    // labels per row
#define NT 256    // threads per block
#define NW 8      // warps per block
#define NC 2      // elements per thread
#define KB 1024   // histogram bins
#define LOV (-8.0f)
#define BW  (0.015625f)   // 1/64
#define INVW (64.0f)

__device__ float g_row[NB];
__device__ int   g_cnt = 0;   // self-resetting across graph replays

__inline__ __device__ float warpSum(float v) {
#pragma unroll
    for (int o = 16; o; o >>= 1) v += __shfl_xor_sync(0xffffffffu, v, o);
    return v;
}

__global__ __launch_bounds__(NT) void row_kernel(const float* __restrict__ outp,
                                                 const int* __restrict__ tgt,
                                                 float* __restrict__ out) {
    __shared__ __align__(16) int    hcnt[KB];   // positive-count histogram
    __shared__ __align__(16) float2 SP[KB];     // inclusive prefix (count, weighted sum)
    __shared__ float wtc[NW], wtw[NW];          // warp scan totals
    __shared__ float s0[NW], s1[NW], s2[NW];
    __shared__ int amLast;

    const int row  = blockIdx.x;
    const int tid  = threadIdx.x;
    const int lane = tid & 31;
    const int wid  = tid >> 5;

    const float* orow = outp + row * NL;
    const int*   trow = tgt  + row * NL;

    // ---- zero histogram (256 threads x int4 = 1024 bins) ----
    reinterpret_cast<int4*>(hcnt)[tid] = make_int4(0, 0, 0, 0);
    __syncthreads();

    // ---- pass 1: load, calib sums (exact fp32), positive histogram (int atomics) ----
    float vv[NC];
    bool  isn[NC];
    float pos_sum = 0.f, neg_sum = 0.f;
#pragma unroll
    for (int c = 0; c < NC; c++) {
        int col = tid + c * NT;
        float v = orow[col];
        bool p  = (trow[col] != 0);
        vv[c] = v; isn[c] = !p;
        if (p) {
            pos_sum += fmaxf(1.f - v, 0.f);
            int b = (int)floorf((v - LOV) * INVW);
            b = min(max(b, 0), KB - 1);
            atomicAdd(&hcnt[b], 1);
        } else {
            neg_sum += fmaxf(1.f + v, 0.f);
        }
    }
    __syncthreads();

    // ---- block scan: thread t owns bins 4t..4t+3; scan count and count*center ----
    int4 c4 = reinterpret_cast<const int4*>(hcnt)[tid];
    float ctr = LOV + ((float)(4 * tid) + 0.5f) * BW;   // center of bin 4t
    float f0 = (float)c4.x, f1 = (float)c4.y, f2 = (float)c4.z, f3 = (float)c4.w;
    float w0 = f0 * ctr;
    float w1 = f1 * (ctr + BW);
    float w2 = f2 * (ctr + 2.f * BW);
    float w3 = f3 * (ctr + 3.f * BW);
    // local inclusive sums
    float ic1 = f0 + f1, ic2 = ic1 + f2, ic3 = ic2 + f3;
    float iw1 = w0 + w1, iw2 = iw1 + w2, iw3 = iw2 + w3;
    // warp inclusive scan of per-thread totals
    float sc = ic3, sw = iw3;
#pragma unroll
    for (int o = 1; o < 32; o <<= 1) {
        float tc = __shfl_up_sync(0xffffffffu, sc, o);
        float tw = __shfl_up_sync(0xffffffffu, sw, o);
        if (lane >= o) { sc += tc; sw += tw; }
    }
    if (lane == 31) { wtc[wid] = sc; wtw[wid] = sw; }
    __syncthreads();

    float offC = 0.f, offW = 0.f, n_pf = 0.f;
#pragma unroll
    for (int i = 0; i < NW; i++) {
        float a = wtc[i], b = wtw[i];
        n_pf += a;                        // grand total = n_p (exact integer in float)
        if (i < wid) { offC += a; offW += b; }
    }
    float exC = offC + sc - ic3;          // exclusive prefix before bin 4t
    float exW = offW + sw - iw3;
    SP[4 * tid + 0] = make_float2(exC + f0,  exW + w0);
    SP[4 * tid + 1] = make_float2(exC + ic1, exW + iw1);
    SP[4 * tid + 2] = make_float2(exC + ic2, exW + iw2);
    SP[4 * tid + 3] = make_float2(exC + ic3, exW + iw3);
    __syncthreads();

    // ---- per-negative O(1) lookup: sum relu(c - p) = c*cntBelow - wsumBelow ----
    float hacc = 0.f;
#pragma unroll
    for (int c = 0; c < NC; c++) {
        if (isn[c]) {
            float cc = 1.f + vv[c];
            // include bins with center < cc
            int m = (int)floorf((cc - LOV) * INVW - 0.5f) + 1;
            m = min(max(m, 0), KB);
            if (m > 0) {
                float2 pw = SP[m - 1];
                hacc = fmaf(cc, pw.x, hacc - pw.y);
            }
        }
    }

    // ---- block reduce (hinge acc, pos_sum, neg_sum) ----
    float r0 = warpSum(hacc);
    float r1 = warpSum(pos_sum);
    float r2 = warpSum(neg_sum);
    if (lane == 0) { s0[wid] = r0; s1[wid] = r1; s2[wid] = r2; }
    __syncthreads();

    if (tid == 0) {
        float ps = 0.f, qs = 0.f, ns = 0.f;
#pragma unroll
        for (int w = 0; w < NW; w++) { ps += s0[w]; qs += s1[w]; ns += s2[w]; }
        int n_p = (int)n_pf;
        int n_n = NL - n_p;
        float pos_calib = (n_p > 0) ? qs / (float)n_p : 0.f;
        float neg_calib = (n_n > 0) ? ns / (float)n_n : 0.f;
        long long denom = (long long)n_p * (long long)n_n;
        float hinge;
        if (denom > 0)      hinge = ps / (float)denom;
        else if (n_p > 0)   hinge = pos_calib;
        else if (n_n > 0)   hinge = neg_calib;
        else                hinge = 1.f;
        g_row[row] = hinge + neg_calib + pos_calib;
        __threadfence();
        int old = atomicAdd(&g_cnt, 1);
        amLast = (old == NB - 1);
    }
    __syncthreads();

    // ---- last block: deterministic final mean over g_row ----
    if (amLast) {
        __threadfence();  // acquire all g_row writes
        float v = 0.f;
#pragma unroll
        for (int i = tid; i < NB; i += NT) v += g_row[i];
        v = warpSum(v);
        if (lane == 0) s0[wid] = v;
        __syncthreads();
        if (tid == 0) {
            float t = 0.f;
#pragma unroll
            for (int w = 0; w < NW; w++) t += s0[w];
            out[0] = t / (float)NB;
            g_cnt = 0;   // reset for next graph replay
        }
    }
}

extern "C" void kernel_launch(void* const* d_in, const int* in_sizes, int n_in,
                              void* d_out, int out_size) {
    const float* outputs = (const float*)d_in[0];
    const int*   targets = (const int*)d_in[1];
    row_kernel<<<NB, NT>>>(outputs, targets, (float*)d_out);
}